// round 10
// baseline (speedup 1.0000x reference)
#include <cuda_runtime.h>
#include <cuda_fp16.h>
#include <cstdint>

// ============================================================
// LocallyConnectedLayer: out[b,o,i,j] = sum_{c,kh,kw} x[b,c,i+kh,j+kw]
//                        * weight[c,o,i,j,kh,kw] + bias[o,i,j]
// B=128, C=64, O=64, H=W=32, OH=OW=30, K=3.
// R10: no weight prepass. lc_main loads its 4096x9-float weight block
// directly from wt (contiguous 36B runs, ~1.9x sector inflation), converts
// to fp16 into 9 resident smem slices, then runs the 9-step HMMA mainloop
// with a 2-stage A ring fed from L2-resident g_Xf. 104KB smem -> 2 CTAs/SM
// (co-resident CTA's MMA overlaps this CTA's DRAM-bound weight prologue).
// ============================================================

#define NPOS 900
#define PW   8100      // NPOS*9

// ---- scratch ----
__device__ __align__(1024) __half g_Xf[(size_t)1024 * 8192];    // [s]: 16KB slice [b*64+c], SW128
__device__ __align__(1024) float  g_Y[(size_t)NPOS * 8192];     // [pos][b*64+o], bias included

// ---- helpers ----
__device__ __forceinline__ uint32_t smem_to_u32(const void* p) {
    uint32_t a;
    asm("{ .reg .u64 t; cvta.to.shared.u64 t, %1; cvt.u32.u64 %0, t; }" : "=r"(a) : "l"(p));
    return a;
}
#define SWZ(off) ((off) ^ (((off) >> 3) & 0x70))

__device__ __forceinline__ void ldsm_x4(uint32_t a[4], uint32_t addr) {
    asm volatile("ldmatrix.sync.aligned.m8n8.x4.shared.b16 {%0,%1,%2,%3}, [%4];"
        : "=r"(a[0]), "=r"(a[1]), "=r"(a[2]), "=r"(a[3]) : "r"(addr));
}
__device__ __forceinline__ void mma_f16(float c[4], const uint32_t a[4], const uint32_t b[2]) {
    asm volatile(
        "mma.sync.aligned.m16n8k16.row.col.f32.f16.f16.f32 "
        "{%0,%1,%2,%3},{%4,%5,%6,%7},{%8,%9},{%0,%1,%2,%3};"
        : "+f"(c[0]), "+f"(c[1]), "+f"(c[2]), "+f"(c[3])
        : "r"(a[0]), "r"(a[1]), "r"(a[2]), "r"(a[3]), "r"(b[0]), "r"(b[1]));
}
#define MBARRIER_INIT(mbar, count) \
    asm volatile("mbarrier.init.shared.b64 [%0], %1;" :: "r"((uint32_t)(mbar)), "r"((uint32_t)(count)) : "memory")
#define MBARRIER_EXPECT_TX(mbar, tx) \
    asm volatile("mbarrier.arrive.expect_tx.shared.b64 _, [%0], %1;" :: "r"((uint32_t)(mbar)), "r"((uint32_t)(tx)) : "memory")
#define MBARRIER_WAIT_PARITY(mbar, parity) do { \
    uint32_t _m = (uint32_t)(mbar); uint32_t _p = (uint32_t)(parity); uint32_t _d; \
    asm volatile("{\n\t.reg .pred p;\n\tmbarrier.try_wait.parity.acquire.cta.shared::cta.b64 p, [%1], %2;\n\tselp.b32 %0, 1, 0, p;\n\t}" \
        : "=r"(_d) : "r"(_m), "r"(_p) : "memory"); \
    if (!_d) { \
        asm volatile("{\n\t.reg .pred P1;\n\tWL_%=:\n\tmbarrier.try_wait.parity.acquire.cta.shared::cta.b64 P1, [%0], %1, 0x989680;\n\t@P1 bra.uni WD_%=;\n\tbra.uni WL_%=;\n\tWD_%=:\n\t}" \
            :: "r"(_m), "r"(_p) : "memory"); \
    } } while (0)
__device__ __forceinline__ void bulk_g2s(uint32_t dst, const void* src, uint32_t bytes, uint32_t mbar) {
    asm volatile(
        "cp.async.bulk.shared::cluster.global.mbarrier::complete_tx::bytes [%0], [%1], %2, [%3];"
        :: "r"(dst), "l"(src), "r"(bytes), "r"(mbar) : "memory");
}

// ============================================================
// Prepass (x only): [bc=8192][s=1024] fp32 -> g_Xf [s][bc] fp16 pre-swizzled.
// 64x64 tiles; float4 loads, smem transpose, uint4 stores.
// ============================================================
__global__ __launch_bounds__(256) void prep_x(const float* __restrict__ x) {
    __shared__ float t[64][65];
    const int tid = threadIdx.x;
    const int s0  = (blockIdx.x & 15) * 64;
    const int bc0 = (blockIdx.x >> 4) * 64;
    #pragma unroll
    for (int k = 0; k < 4; k++) {
        int idx = tid + k * 256;
        int r   = idx >> 4;
        int q   = idx & 15;
        float4 v = *(const float4*)(x + (size_t)(bc0 + r) * 1024 + s0 + q * 4);
        t[r][q * 4 + 0] = v.x; t[r][q * 4 + 1] = v.y;
        t[r][q * 4 + 2] = v.z; t[r][q * 4 + 3] = v.w;
    }
    __syncthreads();
    #pragma unroll
    for (int k = 0; k < 2; k++) {
        int idx = tid + k * 256;
        int sl  = idx >> 3;
        int q8  = idx & 7;
        uint32_t pk[4];
        #pragma unroll
        for (int j = 0; j < 4; j++) {
            __half2 h = __floats2half2_rn(t[q8 * 8 + j * 2][sl], t[q8 * 8 + j * 2 + 1][sl]);
            pk[j] = *(uint32_t*)&h;
        }
        uint32_t off = SWZ((uint32_t)(bc0 * 2 + q8 * 16));
        *(uint4*)((char*)g_Xf + (size_t)(s0 + sl) * 16384 + off) = *(uint4*)pk;
    }
}

// ============================================================
// Main: 900 CTAs (1 pos), 256 threads (4x2 warps, warp tile 32x32).
// smem: A ring 2x16KB (offset 0) + W slices 9x8KB (offset 32KB) = 104KB.
// Prologue: direct strided weight load + fp16 convert into all 9 W slices.
// Mainloop: 9 steps, A via cp.async.bulk from g_Xf, HMMA 16816.
// Epilogue: bias + sector-perfect float2 stores to g_Y[pos][b*64+o].
// ============================================================
#define A_STAGE 16384u
#define W_BASE  32768u
#define SM_TOTAL (32768 + 9 * 8192)   // 106496

__device__ __forceinline__ void issueA(uint32_t sb, uint32_t mb, int oi, int oj, int r) {
    const int s = (oi + r / 3) * 32 + (oj + r % 3);
    const uint32_t mbar = mb + (uint32_t)(r & 1) * 8;
    MBARRIER_EXPECT_TX(mbar, 16384u);
    bulk_g2s(sb + (uint32_t)(r & 1) * A_STAGE,
             (const char*)g_Xf + (size_t)s * 16384, 16384u, mbar);
}

__global__ __launch_bounds__(256, 2) void lc_main(const float* __restrict__ wt,
                                                  const float* __restrict__ bias) {
    extern __shared__ __align__(1024) char smem[];
    __shared__ __align__(8) uint64_t mbar_s[2];
    const uint32_t sb = smem_to_u32(smem);
    const uint32_t mb = smem_to_u32(mbar_s);
    const int tid  = threadIdx.x;
    const int lane = tid & 31;
    const int warp = tid >> 5;
    const int wm   = warp & 3;    // 4 warps along M (batch)
    const int wn   = warp >> 2;   // 2 warps along N (out-ch)
    const int pos  = blockIdx.x;
    const int oi   = pos / 30;
    const int oj   = pos % 30;

    if (tid == 0) { MBARRIER_INIT(mb, 1); MBARRIER_INIT(mb + 8, 1); }
    __syncthreads();
    if (tid == 0) { issueA(sb, mb, oi, oj, 0); issueA(sb, mb, oi, oj, 1); }

    // ---- weight prologue: warp handles o = warp*8 + i, lane handles c-pair.
    // Each (c,o) row: 9 contiguous fp32 -> half2 packed with c+1 row -> STS.32
    // into slice r at SWZ(o*128 + lane*4). Conflict-free (XOR const per o).
    {
        const size_t row0 = (size_t)(2 * lane) * 64;   // c = 2*lane
        #pragma unroll 2
        for (int i = 0; i < 8; i++) {
            const int o = warp * 8 + i;
            const float* wr = wt + (row0 + o) * PW + pos * 9;
            float a0[9], a1[9];
            #pragma unroll
            for (int k = 0; k < 9; k++) a0[k] = wr[k];
            #pragma unroll
            for (int k = 0; k < 9; k++) a1[k] = wr[(size_t)64 * PW + k];
            const uint32_t so = SWZ((uint32_t)(o * 128 + lane * 4));
            #pragma unroll
            for (int k = 0; k < 9; k++) {
                __half2 h = __floats2half2_rn(a0[k], a1[k]);
                *(uint32_t*)(smem + W_BASE + (uint32_t)k * 8192u + so) = *(uint32_t*)&h;
            }
        }
    }
    __syncthreads();   // W slices ready for all warps

    // ---- ldmatrix lane addressing ----
    const int rowA = lane & 15;
    const uint32_t a_cs = (uint32_t)(lane >> 4) * 16;
    const uint32_t a_xm = (uint32_t)(rowA & 7) << 4;
    uint32_t a_row[2];
    #pragma unroll
    for (int mt = 0; mt < 2; mt++)
        a_row[mt] = (uint32_t)(wm * 32 + mt * 16 + rowA) * 128;

    const int rowB = (lane & 7) + ((lane >> 4) << 3);
    const uint32_t b_cs = (uint32_t)((lane >> 3) & 1) * 16;
    const uint32_t b_xm = (uint32_t)(lane & 7) << 4;
    uint32_t b_row[2];
    #pragma unroll
    for (int np = 0; np < 2; np++)
        b_row[np] = (uint32_t)(wn * 32 + np * 16 + rowB) * 128;

    float acc[2][4][4];
    #pragma unroll
    for (int mt = 0; mt < 2; mt++)
        #pragma unroll
        for (int nt = 0; nt < 4; nt++)
            #pragma unroll
            for (int e = 0; e < 4; e++) acc[mt][nt][e] = 0.f;

    // ---- mainloop: 9 r-steps, 2-stage A ring ----
    for (int r = 0; r < 9; r++) {
        MBARRIER_WAIT_PARITY(mb + (uint32_t)(r & 1) * 8, (uint32_t)((r >> 1) & 1));
        const uint32_t abase = sb + (uint32_t)(r & 1) * A_STAGE;
        const uint32_t wbase = sb + W_BASE + (uint32_t)r * 8192u;
        #pragma unroll
        for (int kk = 0; kk < 4; kk++) {
            const uint32_t acol = ((uint32_t)(kk * 32) + a_cs) ^ a_xm;
            const uint32_t bcol = ((uint32_t)(kk * 32) + b_cs) ^ b_xm;
            uint32_t A[2][4], Bm[2][4];
            #pragma unroll
            for (int mt = 0; mt < 2; mt++)
                ldsm_x4(A[mt], abase + a_row[mt] + acol);
            #pragma unroll
            for (int np = 0; np < 2; np++)
                ldsm_x4(Bm[np], wbase + b_row[np] + bcol);
            #pragma unroll
            for (int mt = 0; mt < 2; mt++)
                #pragma unroll
                for (int nt = 0; nt < 4; nt++)
                    mma_f16(acc[mt][nt], A[mt], &Bm[nt >> 1][(nt & 1) * 2]);
        }
        __syncthreads();
        if (tid == 0 && r + 2 < 9) issueA(sb, mb, oi, oj, r + 2);
    }

    // ---- epilogue: bias + sector-perfect float2 stores to g_Y[pos][b*64+o] ----
    float bv[4][2];
    #pragma unroll
    for (int nt = 0; nt < 4; nt++)
        #pragma unroll
        for (int cc = 0; cc < 2; cc++)
            bv[nt][cc] = bias[(size_t)(wn * 32 + nt * 8 + (lane & 3) * 2 + cc) * NPOS + pos];
    float* yp = g_Y + (size_t)pos * 8192;
    #pragma unroll
    for (int mt = 0; mt < 2; mt++)
        #pragma unroll
        for (int half = 0; half < 2; half++) {
            const int b = wm * 32 + mt * 16 + (lane >> 2) + half * 8;
            #pragma unroll
            for (int nt = 0; nt < 4; nt++) {
                const int o0 = wn * 32 + nt * 8 + (lane & 3) * 2;
                float2 v;
                v.x = acc[mt][nt][half * 2 + 0] + bv[nt][0];
                v.y = acc[mt][nt][half * 2 + 1] + bv[nt][1];
                *(float2*)(yp + b * 64 + o0) = v;
            }
        }
}

// ============================================================
// Transpose: g_Y[pos][bo] -> out[bo][pos]. 36x128 tiles (exact).
// ============================================================
__global__ __launch_bounds__(256) void lc_tr(float* __restrict__ out) {
    __shared__ float t[36][130];
    const int tid  = threadIdx.x;
    const int pos0 = blockIdx.x * 36;
    const int bo0  = blockIdx.y * 128;
    #pragma unroll
    for (int k = 0; k < 5; k++) {
        int idx = tid + k * 256;
        if (idx < 1152) {
            int p = idx >> 5, q = idx & 31;
            float4 v = *(const float4*)(g_Y + (size_t)(pos0 + p) * 8192 + bo0 + q * 4);
            t[p][q * 4 + 0] = v.x; t[p][q * 4 + 1] = v.y;
            t[p][q * 4 + 2] = v.z; t[p][q * 4 + 3] = v.w;
        }
    }
    __syncthreads();
    #pragma unroll
    for (int k = 0; k < 5; k++) {
        int idx = tid + k * 256;
        if (idx < 1152) {
            int f  = idx % 9;
            int bo = idx / 9;
            float4 v;
            v.x = t[f * 4 + 0][bo];
            v.y = t[f * 4 + 1][bo];
            v.z = t[f * 4 + 2][bo];
            v.w = t[f * 4 + 3][bo];
            *(float4*)(out + (size_t)(bo0 + bo) * NPOS + pos0 + f * 4) = v;
        }
    }
}

// ============================================================
extern "C" void kernel_launch(void* const* d_in, const int* in_sizes, int n_in,
                              void* d_out, int out_size) {
    const float* x    = (const float*)d_in[0];   // [128,64,32,32]
    const float* wt   = (const float*)d_in[1];   // [64,64,30,30,3,3]
    const float* bias = (const float*)d_in[2];   // [64,30,30]
    float* out = (float*)d_out;                  // [128,64,30,30]

    cudaFuncSetAttribute(lc_main, cudaFuncAttributeMaxDynamicSharedMemorySize, SM_TOTAL);

    prep_x<<<2048, 256>>>(x);
    lc_main<<<NPOS, 256, SM_TOTAL>>>(wt, bias);
    lc_tr<<<dim3(25, 64), 256>>>(out);
}

// round 11
// speedup vs baseline: 1.1008x; 1.1008x over previous
#include <cuda_runtime.h>
#include <cuda_fp16.h>
#include <cstdint>

// ============================================================
// LocallyConnectedLayer: out[b,o,i,j] = sum_{c,kh,kw} x[b,c,i+kh,j+kw]
//                        * weight[c,o,i,j,kh,kw] + bias[o,i,j]
// B=128, C=64, O=64, H=W=32, OH=OW=30, K=3.
// R11: direct weight gather (no prep_w), L1tex-friendly mapping:
// lanes 0..26 = 3 rows x 9 k-words per warp-LDG (nL~4, not 32).
// fp32 -> fp16 -> STS.u16 into 9 resident W slices (pitch 8208).
// Mainloop/epilogue identical to R9/R10 (2-stage A ring from g_Xf,
// g_Y staging, separate transpose kernel).
// ============================================================

#define NPOS 900
#define PW   8100      // NPOS*9

// ---- scratch ----
__device__ __align__(1024) __half g_Xf[(size_t)1024 * 8192];    // [s]: 16KB slice [b*64+c], SW128
__device__ __align__(1024) float  g_Y[(size_t)NPOS * 8192];     // [pos][b*64+o], bias included

// ---- helpers ----
__device__ __forceinline__ uint32_t smem_to_u32(const void* p) {
    uint32_t a;
    asm("{ .reg .u64 t; cvta.to.shared.u64 t, %1; cvt.u32.u64 %0, t; }" : "=r"(a) : "l"(p));
    return a;
}
#define SWZ(off) ((off) ^ (((off) >> 3) & 0x70))

__device__ __forceinline__ void ldsm_x4(uint32_t a[4], uint32_t addr) {
    asm volatile("ldmatrix.sync.aligned.m8n8.x4.shared.b16 {%0,%1,%2,%3}, [%4];"
        : "=r"(a[0]), "=r"(a[1]), "=r"(a[2]), "=r"(a[3]) : "r"(addr));
}
__device__ __forceinline__ void mma_f16(float c[4], const uint32_t a[4], const uint32_t b[2]) {
    asm volatile(
        "mma.sync.aligned.m16n8k16.row.col.f32.f16.f16.f32 "
        "{%0,%1,%2,%3},{%4,%5,%6,%7},{%8,%9},{%0,%1,%2,%3};"
        : "+f"(c[0]), "+f"(c[1]), "+f"(c[2]), "+f"(c[3])
        : "r"(a[0]), "r"(a[1]), "r"(a[2]), "r"(a[3]), "r"(b[0]), "r"(b[1]));
}
#define MBARRIER_INIT(mbar, count) \
    asm volatile("mbarrier.init.shared.b64 [%0], %1;" :: "r"((uint32_t)(mbar)), "r"((uint32_t)(count)) : "memory")
#define MBARRIER_EXPECT_TX(mbar, tx) \
    asm volatile("mbarrier.arrive.expect_tx.shared.b64 _, [%0], %1;" :: "r"((uint32_t)(mbar)), "r"((uint32_t)(tx)) : "memory")
#define MBARRIER_WAIT_PARITY(mbar, parity) do { \
    uint32_t _m = (uint32_t)(mbar); uint32_t _p = (uint32_t)(parity); uint32_t _d; \
    asm volatile("{\n\t.reg .pred p;\n\tmbarrier.try_wait.parity.acquire.cta.shared::cta.b64 p, [%1], %2;\n\tselp.b32 %0, 1, 0, p;\n\t}" \
        : "=r"(_d) : "r"(_m), "r"(_p) : "memory"); \
    if (!_d) { \
        asm volatile("{\n\t.reg .pred P1;\n\tWL_%=:\n\tmbarrier.try_wait.parity.acquire.cta.shared::cta.b64 P1, [%0], %1, 0x989680;\n\t@P1 bra.uni WD_%=;\n\tbra.uni WL_%=;\n\tWD_%=:\n\t}" \
            :: "r"(_m), "r"(_p) : "memory"); \
    } } while (0)
__device__ __forceinline__ void bulk_g2s(uint32_t dst, const void* src, uint32_t bytes, uint32_t mbar) {
    asm volatile(
        "cp.async.bulk.shared::cluster.global.mbarrier::complete_tx::bytes [%0], [%1], %2, [%3];"
        :: "r"(dst), "l"(src), "r"(bytes), "r"(mbar) : "memory");
}

// ============================================================
// Prepass (x only): [bc=8192][s=1024] fp32 -> g_Xf [s][bc] fp16 pre-swizzled.
// ============================================================
__global__ __launch_bounds__(256) void prep_x(const float* __restrict__ x) {
    __shared__ float t[64][65];
    const int tid = threadIdx.x;
    const int s0  = (blockIdx.x & 15) * 64;
    const int bc0 = (blockIdx.x >> 4) * 64;
    #pragma unroll
    for (int k = 0; k < 4; k++) {
        int idx = tid + k * 256;
        int r   = idx >> 4;
        int q   = idx & 15;
        float4 v = *(const float4*)(x + (size_t)(bc0 + r) * 1024 + s0 + q * 4);
        t[r][q * 4 + 0] = v.x; t[r][q * 4 + 1] = v.y;
        t[r][q * 4 + 2] = v.z; t[r][q * 4 + 3] = v.w;
    }
    __syncthreads();
    #pragma unroll
    for (int k = 0; k < 2; k++) {
        int idx = tid + k * 256;
        int sl  = idx >> 3;
        int q8  = idx & 7;
        uint32_t pk[4];
        #pragma unroll
        for (int j = 0; j < 4; j++) {
            __half2 h = __floats2half2_rn(t[q8 * 8 + j * 2][sl], t[q8 * 8 + j * 2 + 1][sl]);
            pk[j] = *(uint32_t*)&h;
        }
        uint32_t off = SWZ((uint32_t)(bc0 * 2 + q8 * 16));
        *(uint4*)((char*)g_Xf + (size_t)(s0 + sl) * 16384 + off) = *(uint4*)pk;
    }
}

// ============================================================
// Main: 900 CTAs (1 pos), 256 threads (4x2 warps, warp tile 32x32).
// smem: A ring 2x16KB (offset 0) + 9 W slices pitch 8208 at 32KB = ~104KB.
// Prologue: warp-cooperative gather — lane l<27 -> (dr=l/9, k=l%9),
//   3 consecutive rows x 9 words per LDG instruction (nL~4), cvt fp16,
//   STS.u16 into slice k at SWZ(o*128 + c*2).
// ============================================================
#define A_STAGE 16384u
#define W_BASE  32768u
#define W_PITCH 8208u                       // 8192 + 16: 16B-aligned, bank-spread
#define SM_TOTAL (32768 + 9 * 8208)         // 106640

__device__ __forceinline__ void issueA(uint32_t sb, uint32_t mb, int oi, int oj, int r) {
    const int s = (oi + r / 3) * 32 + (oj + r % 3);
    const uint32_t mbar = mb + (uint32_t)(r & 1) * 8;
    MBARRIER_EXPECT_TX(mbar, 16384u);
    bulk_g2s(sb + (uint32_t)(r & 1) * A_STAGE,
             (const char*)g_Xf + (size_t)s * 16384, 16384u, mbar);
}

__global__ __launch_bounds__(256, 2) void lc_main(const float* __restrict__ wt,
                                                  const float* __restrict__ bias) {
    extern __shared__ __align__(1024) char smem[];
    __shared__ __align__(8) uint64_t mbar_s[2];
    const uint32_t sb = smem_to_u32(smem);
    const uint32_t mb = smem_to_u32(mbar_s);
    const int tid  = threadIdx.x;
    const int lane = tid & 31;
    const int warp = tid >> 5;
    const int wm   = warp & 3;    // 4 warps along M (batch)
    const int wn   = warp >> 2;   // 2 warps along N (out-ch)
    const int pos  = blockIdx.x;
    const int oi   = pos / 30;
    const int oj   = pos % 30;

    if (tid == 0) { MBARRIER_INIT(mb, 1); MBARRIER_INIT(mb + 8, 1); }
    __syncthreads();
    if (tid == 0) { issueA(sb, mb, oi, oj, 0); issueA(sb, mb, oi, oj, 1); }

    // ---- weight gather prologue ----
    // warp w owns rows [512w, 512w+512); lane l<27: dr = l/9 in 0..2, k = l%9.
    // Per iteration: 3 consecutive rows' full 36B read by 27 lanes (nL~4).
    {
        const int dr = lane / 9;           // 0..2 (lane 27..31 idle)
        const int kw = lane - dr * 9;      // 0..8
        const bool active = lane < 27;
        const float* base = wt + (size_t)warp * 512 * PW + pos * 9 + kw;
        #pragma unroll 4
        for (int it = 0; it < 171; it++) {
            const int rl = it * 3 + dr;    // row within warp's 512
            if (active && rl < 512) {
                float v = base[(size_t)rl * PW];
                const int row = warp * 512 + rl;     // c*64 + o
                const int o = row & 63;
                const int c = row >> 6;
                const uint32_t so = SWZ((uint32_t)(o * 128 + c * 2));
                *(__half*)(smem + W_BASE + (uint32_t)kw * W_PITCH + so) = __float2half(v);
            }
        }
    }
    __syncthreads();   // W slices ready

    // ---- ldmatrix lane addressing ----
    const int rowA = lane & 15;
    const uint32_t a_cs = (uint32_t)(lane >> 4) * 16;
    const uint32_t a_xm = (uint32_t)(rowA & 7) << 4;
    uint32_t a_row[2];
    #pragma unroll
    for (int mt = 0; mt < 2; mt++)
        a_row[mt] = (uint32_t)(wm * 32 + mt * 16 + rowA) * 128;

    const int rowB = (lane & 7) + ((lane >> 4) << 3);
    const uint32_t b_cs = (uint32_t)((lane >> 3) & 1) * 16;
    const uint32_t b_xm = (uint32_t)(lane & 7) << 4;
    uint32_t b_row[2];
    #pragma unroll
    for (int np = 0; np < 2; np++)
        b_row[np] = (uint32_t)(wn * 32 + np * 16 + rowB) * 128;

    float acc[2][4][4];
    #pragma unroll
    for (int mt = 0; mt < 2; mt++)
        #pragma unroll
        for (int nt = 0; nt < 4; nt++)
            #pragma unroll
            for (int e = 0; e < 4; e++) acc[mt][nt][e] = 0.f;

    // ---- mainloop: 9 r-steps, 2-stage A ring ----
    for (int r = 0; r < 9; r++) {
        MBARRIER_WAIT_PARITY(mb + (uint32_t)(r & 1) * 8, (uint32_t)((r >> 1) & 1));
        const uint32_t abase = sb + (uint32_t)(r & 1) * A_STAGE;
        const uint32_t wbase = sb + W_BASE + (uint32_t)r * W_PITCH;
        #pragma unroll
        for (int kk = 0; kk < 4; kk++) {
            const uint32_t acol = ((uint32_t)(kk * 32) + a_cs) ^ a_xm;
            const uint32_t bcol = ((uint32_t)(kk * 32) + b_cs) ^ b_xm;
            uint32_t A[2][4], Bm[2][4];
            #pragma unroll
            for (int mt = 0; mt < 2; mt++)
                ldsm_x4(A[mt], abase + a_row[mt] + acol);
            #pragma unroll
            for (int np = 0; np < 2; np++)
                ldsm_x4(Bm[np], wbase + b_row[np] + bcol);
            #pragma unroll
            for (int mt = 0; mt < 2; mt++)
                #pragma unroll
                for (int nt = 0; nt < 4; nt++)
                    mma_f16(acc[mt][nt], A[mt], &Bm[nt >> 1][(nt & 1) * 2]);
        }
        __syncthreads();
        if (tid == 0 && r + 2 < 9) issueA(sb, mb, oi, oj, r + 2);
    }

    // ---- epilogue: bias + sector-perfect float2 stores to g_Y[pos][b*64+o] ----
    float bv[4][2];
    #pragma unroll
    for (int nt = 0; nt < 4; nt++)
        #pragma unroll
        for (int cc = 0; cc < 2; cc++)
            bv[nt][cc] = bias[(size_t)(wn * 32 + nt * 8 + (lane & 3) * 2 + cc) * NPOS + pos];
    float* yp = g_Y + (size_t)pos * 8192;
    #pragma unroll
    for (int mt = 0; mt < 2; mt++)
        #pragma unroll
        for (int half = 0; half < 2; half++) {
            const int b = wm * 32 + mt * 16 + (lane >> 2) + half * 8;
            #pragma unroll
            for (int nt = 0; nt < 4; nt++) {
                const int o0 = wn * 32 + nt * 8 + (lane & 3) * 2;
                float2 v;
                v.x = acc[mt][nt][half * 2 + 0] + bv[nt][0];
                v.y = acc[mt][nt][half * 2 + 1] + bv[nt][1];
                *(float2*)(yp + b * 64 + o0) = v;
            }
        }
}

// ============================================================
// Transpose: g_Y[pos][bo] -> out[bo][pos]. 36x128 tiles (exact).
// ============================================================
__global__ __launch_bounds__(256) void lc_tr(float* __restrict__ out) {
    __shared__ float t[36][130];
    const int tid  = threadIdx.x;
    const int pos0 = blockIdx.x * 36;
    const int bo0  = blockIdx.y * 128;
    #pragma unroll
    for (int k = 0; k < 5; k++) {
        int idx = tid + k * 256;
        if (idx < 1152) {
            int p = idx >> 5, q = idx & 31;
            float4 v = *(const float4*)(g_Y + (size_t)(pos0 + p) * 8192 + bo0 + q * 4);
            t[p][q * 4 + 0] = v.x; t[p][q * 4 + 1] = v.y;
            t[p][q * 4 + 2] = v.z; t[p][q * 4 + 3] = v.w;
        }
    }
    __syncthreads();
    #pragma unroll
    for (int k = 0; k < 5; k++) {
        int idx = tid + k * 256;
        if (idx < 1152) {
            int f  = idx % 9;
            int bo = idx / 9;
            float4 v;
            v.x = t[f * 4 + 0][bo];
            v.y = t[f * 4 + 1][bo];
            v.z = t[f * 4 + 2][bo];
            v.w = t[f * 4 + 3][bo];
            *(float4*)(out + (size_t)(bo0 + bo) * NPOS + pos0 + f * 4) = v;
        }
    }
}

// ============================================================
extern "C" void kernel_launch(void* const* d_in, const int* in_sizes, int n_in,
                              void* d_out, int out_size) {
    const float* x    = (const float*)d_in[0];   // [128,64,32,32]
    const float* wt   = (const float*)d_in[1];   // [64,64,30,30,3,3]
    const float* bias = (const float*)d_in[2];   // [64,30,30]
    float* out = (float*)d_out;                  // [128,64,30,30]

    cudaFuncSetAttribute(lc_main, cudaFuncAttributeMaxDynamicSharedMemorySize, SM_TOTAL);

    prep_x<<<2048, 256>>>(x);
    lc_main<<<NPOS, 256, SM_TOTAL>>>(wt, bias);
    lc_tr<<<dim3(25, 64), 256>>>(out);
}

// round 12
// speedup vs baseline: 1.9748x; 1.7939x over previous
#include <cuda_runtime.h>
#include <cuda_fp16.h>
#include <cstdint>

// ============================================================
// LocallyConnectedLayer (B=128, C=64, O=64, 30x30 pos, K=3).
// R12: R9 dataflow (coalesced prep -> pre-swizzled fp16 slices -> 9-step
// HMMA mainloop -> g_Y staging -> transpose), but prep and main FUSED into
// one kernel: producer blocks first, consumer blocks spin on per-tile
// completion counters -> prep/main pipeline instead of serializing.
// ============================================================

#define NPOS 900
#define PW   8100      // NPOS*9

// ---- scratch ----
__device__ __align__(1024) __half g_Wf[(size_t)PW * 64 * 64];   // [P]: 8KB slice [o][c], SW128
__device__ __align__(1024) __half g_Xf[(size_t)1024 * 8192];    // [s]: 16KB slice [b*64+c], SW128
__device__ __align__(1024) float  g_Y[(size_t)NPOS * 8192];     // [pos][b*64+o]
__device__ int g_wcnt[127];
__device__ int g_xcnt;

#define NXBLK 2048
#define NWBLK 8128     // 127 tiles * 64 o-blocks (o-contiguous per tile)

// ---- helpers ----
__device__ __forceinline__ uint32_t smem_to_u32(const void* p) {
    uint32_t a;
    asm("{ .reg .u64 t; cvta.to.shared.u64 t, %1; cvt.u32.u64 %0, t; }" : "=r"(a) : "l"(p));
    return a;
}
#define SWZ(off) ((off) ^ (((off) >> 3) & 0x70))

__device__ __forceinline__ void ldsm_x4(uint32_t a[4], uint32_t addr) {
    asm volatile("ldmatrix.sync.aligned.m8n8.x4.shared.b16 {%0,%1,%2,%3}, [%4];"
        : "=r"(a[0]), "=r"(a[1]), "=r"(a[2]), "=r"(a[3]) : "r"(addr));
}
__device__ __forceinline__ void mma_f16(float c[4], const uint32_t a[4], const uint32_t b[2]) {
    asm volatile(
        "mma.sync.aligned.m16n8k16.row.col.f32.f16.f16.f32 "
        "{%0,%1,%2,%3},{%4,%5,%6,%7},{%8,%9},{%0,%1,%2,%3};"
        : "+f"(c[0]), "+f"(c[1]), "+f"(c[2]), "+f"(c[3])
        : "r"(a[0]), "r"(a[1]), "r"(a[2]), "r"(a[3]), "r"(b[0]), "r"(b[1]));
}
#define MBARRIER_INIT(mbar, count) \
    asm volatile("mbarrier.init.shared.b64 [%0], %1;" :: "r"((uint32_t)(mbar)), "r"((uint32_t)(count)) : "memory")
#define MBARRIER_EXPECT_TX(mbar, tx) \
    asm volatile("mbarrier.arrive.expect_tx.shared.b64 _, [%0], %1;" :: "r"((uint32_t)(mbar)), "r"((uint32_t)(tx)) : "memory")
#define MBARRIER_WAIT_PARITY(mbar, parity) do { \
    uint32_t _m = (uint32_t)(mbar); uint32_t _p = (uint32_t)(parity); uint32_t _d; \
    asm volatile("{\n\t.reg .pred p;\n\tmbarrier.try_wait.parity.acquire.cta.shared::cta.b64 p, [%1], %2;\n\tselp.b32 %0, 1, 0, p;\n\t}" \
        : "=r"(_d) : "r"(_m), "r"(_p) : "memory"); \
    if (!_d) { \
        asm volatile("{\n\t.reg .pred P1;\n\tWL_%=:\n\tmbarrier.try_wait.parity.acquire.cta.shared::cta.b64 P1, [%0], %1, 0x989680;\n\t@P1 bra.uni WD_%=;\n\tbra.uni WL_%=;\n\tWD_%=:\n\t}" \
            :: "r"(_m), "r"(_p) : "memory"); \
    } } while (0)
__device__ __forceinline__ void bulk_g2s(uint32_t dst, const void* src, uint32_t bytes, uint32_t mbar) {
    asm volatile(
        "cp.async.bulk.shared::cluster.global.mbarrier::complete_tx::bytes [%0], [%1], %2, [%3];"
        :: "r"(dst), "l"(src), "r"(bytes), "r"(mbar) : "memory");
}

// ============================================================
// Reset counters (runs first each replay — keeps graph deterministic)
// ============================================================
__global__ void lc_reset() {
    if (threadIdx.x < 127) g_wcnt[threadIdx.x] = 0;
    if (threadIdx.x == 127) g_xcnt = 0;
}

// ============================================================
// Fused kernel. Block roles by blockIdx.x:
//  [0, NXBLK)                : x producers (64s x 64bc transpose tiles)
//  [NXBLK, NXBLK+NWBLK)      : w producers; i = b-NXBLK, o = i&63, tp = i>>6
//  [NXBLK+NWBLK, +NPOS)      : consumers (1 pos each; spin on deps)
// Dynamic smem = 72KB: producers use 16.9KB of it; consumers 3x24KB ring.
// ============================================================
#define A_STAGE 16384u
#define STAGE   24576u
#define SM_TOTAL (3 * 24576)

__device__ __forceinline__ void issueA(uint32_t sb, uint32_t mb, int oi, int oj, int r) {
    const int s = (oi + r / 3) * 32 + (oj + r % 3);
    const int b = r % 3;
    const uint32_t mbar = mb + (uint32_t)b * 8;
    MBARRIER_EXPECT_TX(mbar, 24576u);
    bulk_g2s(sb + (uint32_t)b * STAGE,
             (const char*)g_Xf + (size_t)s * 16384, 16384u, mbar);
    bulk_g2s(sb + (uint32_t)b * STAGE + 16384u,
             (const char*)g_Wf + (size_t)0, 8192u, mbar);   // patched below
}

__global__ __launch_bounds__(256, 3) void lc_fused(const float* __restrict__ wt,
                                                   const float* __restrict__ x,
                                                   const float* __restrict__ bias) {
    extern __shared__ __align__(1024) char smem[];
    const int tid = threadIdx.x;
    const int bi  = blockIdx.x;

    if (bi < NXBLK + NWBLK) {
        // ================= producer =================
        float (*t)[65] = (float (*)[65])smem;
        if (bi < NXBLK) {
            // ---- x: tile = 64 s x 64 bc ----
            const int s0  = (bi & 15) * 64;
            const int bc0 = (bi >> 4) * 64;
            #pragma unroll
            for (int k = 0; k < 4; k++) {
                int idx = tid + k * 256;
                int r   = idx >> 4;
                int q   = idx & 15;
                float4 v = *(const float4*)(x + (size_t)(bc0 + r) * 1024 + s0 + q * 4);
                t[r][q * 4 + 0] = v.x; t[r][q * 4 + 1] = v.y;
                t[r][q * 4 + 2] = v.z; t[r][q * 4 + 3] = v.w;
            }
            __syncthreads();
            #pragma unroll
            for (int k = 0; k < 2; k++) {
                int idx = tid + k * 256;
                int sl  = idx >> 3;
                int q8  = idx & 7;
                uint32_t pk[4];
                #pragma unroll
                for (int j = 0; j < 4; j++) {
                    __half2 h = __floats2half2_rn(t[q8 * 8 + j * 2][sl], t[q8 * 8 + j * 2 + 1][sl]);
                    pk[j] = *(uint32_t*)&h;
                }
                uint32_t off = SWZ((uint32_t)(bc0 * 2 + q8 * 16));
                *(uint4*)((char*)g_Xf + (size_t)(s0 + sl) * 16384 + off) = *(uint4*)pk;
            }
            __threadfence();
            __syncthreads();
            if (tid == 0) atomicAdd(&g_xcnt, 1);
        } else {
            // ---- w: tile tp (64 P-rows) for one o ----
            const int i  = bi - NXBLK;
            const int o  = i & 63;
            const int tp = i >> 6;
            const int P0 = tp * 64;
            #pragma unroll
            for (int k = 0; k < 4; k++) {
                int idx = tid + k * 256;
                int c   = idx >> 4;
                int q   = idx & 15;
                int P   = P0 + q * 4;
                const float* src = wt + (size_t)(c * 64 + o) * PW + P;
                float4 v;
                if (P + 3 < PW) v = *(const float4*)src;
                else {
                    v.x = (P     < PW) ? src[0] : 0.f;
                    v.y = (P + 1 < PW) ? src[1] : 0.f;
                    v.z = (P + 2 < PW) ? src[2] : 0.f;
                    v.w = (P + 3 < PW) ? src[3] : 0.f;
                }
                t[c][q * 4 + 0] = v.x; t[c][q * 4 + 1] = v.y;
                t[c][q * 4 + 2] = v.z; t[c][q * 4 + 3] = v.w;
            }
            __syncthreads();
            #pragma unroll
            for (int k = 0; k < 2; k++) {
                int idx = tid + k * 256;
                int pl  = idx >> 3;
                int q8  = idx & 7;
                int P   = P0 + pl;
                if (P < PW) {
                    uint32_t pk[4];
                    #pragma unroll
                    for (int j = 0; j < 4; j++) {
                        __half2 h = __floats2half2_rn(t[q8 * 8 + j * 2][pl], t[q8 * 8 + j * 2 + 1][pl]);
                        pk[j] = *(uint32_t*)&h;
                    }
                    uint32_t off = SWZ((uint32_t)(o * 128 + q8 * 16));
                    *(uint4*)((char*)g_Wf + (size_t)P * 8192 + off) = *(uint4*)pk;
                }
            }
            __threadfence();
            __syncthreads();
            if (tid == 0) atomicAdd(&g_wcnt[tp], 1);
        }
        return;
    }

    // ================= consumer =================
    __shared__ __align__(8) uint64_t mbar_s[3];
    const uint32_t sb = smem_to_u32(smem);
    const uint32_t mb = smem_to_u32(mbar_s);
    const int lane = tid & 31;
    const int warp = tid >> 5;
    const int wm   = warp & 3;    // 4 warps along M (batch)
    const int wn   = warp >> 2;   // 2 warps along N (out-ch)
    const int pos  = bi - (NXBLK + NWBLK);
    const int oi   = pos / 30;
    const int oj   = pos % 30;
    const int t0   = (pos * 9) / 64;
    const int t1   = (pos * 9 + 8) / 64;

    if (tid == 0) {
        MBARRIER_INIT(mb, 1); MBARRIER_INIT(mb + 8, 1); MBARRIER_INIT(mb + 16, 1);
        // spin until dependencies complete (producers are earlier blocks)
        while (atomicAdd(&g_xcnt, 0) < NXBLK) __nanosleep(128);
        while (atomicAdd(&g_wcnt[t0], 0) < 64) __nanosleep(128);
        if (t1 != t0)
            while (atomicAdd(&g_wcnt[t1], 0) < 64) __nanosleep(128);
        __threadfence();
    }
    __syncthreads();

    // issue first 3 stages (A 16KB + W 8KB each)
    if (tid == 0) {
        #pragma unroll
        for (int r = 0; r < 3; r++) {
            const int s = (oi + r / 3) * 32 + (oj + r % 3);
            const uint32_t mbar = mb + (uint32_t)r * 8;
            MBARRIER_EXPECT_TX(mbar, 24576u);
            bulk_g2s(sb + (uint32_t)r * STAGE,
                     (const char*)g_Xf + (size_t)s * 16384, 16384u, mbar);
            bulk_g2s(sb + (uint32_t)r * STAGE + 16384u,
                     (const char*)g_Wf + (size_t)(pos * 9 + r) * 8192, 8192u, mbar);
        }
    }

    const int rowA = lane & 15;
    const uint32_t a_cs = (uint32_t)(lane >> 4) * 16;
    const uint32_t a_xm = (uint32_t)(rowA & 7) << 4;
    uint32_t a_row[2];
    #pragma unroll
    for (int mt = 0; mt < 2; mt++)
        a_row[mt] = (uint32_t)(wm * 32 + mt * 16 + rowA) * 128;

    const int rowB = (lane & 7) + ((lane >> 4) << 3);
    const uint32_t b_cs = (uint32_t)((lane >> 3) & 1) * 16;
    const uint32_t b_xm = (uint32_t)(lane & 7) << 4;
    uint32_t b_row[2];
    #pragma unroll
    for (int np = 0; np < 2; np++)
        b_row[np] = (uint32_t)(wn * 32 + np * 16 + rowB) * 128;

    float acc[2][4][4];
    #pragma unroll
    for (int mt = 0; mt < 2; mt++)
        #pragma unroll
        for (int nt = 0; nt < 4; nt++)
            #pragma unroll
            for (int e = 0; e < 4; e++) acc[mt][nt][e] = 0.f;

    uint32_t ph = 0;
    for (int r = 0; r < 9; r++) {
        const int b = r % 3;
        const uint32_t pb = (ph >> b) & 1u;
        ph ^= 1u << b;
        MBARRIER_WAIT_PARITY(mb + (uint32_t)b * 8, pb);
        const uint32_t abase = sb + (uint32_t)b * STAGE;
        const uint32_t wbase = abase + 16384u;
        #pragma unroll
        for (int kk = 0; kk < 4; kk++) {
            const uint32_t acol = ((uint32_t)(kk * 32) + a_cs) ^ a_xm;
            const uint32_t bcol = ((uint32_t)(kk * 32) + b_cs) ^ b_xm;
            uint32_t A[2][4], Bm[2][4];
            #pragma unroll
            for (int mt = 0; mt < 2; mt++)
                ldsm_x4(A[mt], abase + a_row[mt] + acol);
            #pragma unroll
            for (int np = 0; np < 2; np++)
                ldsm_x4(Bm[np], wbase + b_row[np] + bcol);
            #pragma unroll
            for (int mt = 0; mt < 2; mt++)
                #pragma unroll
                for (int nt = 0; nt < 4; nt++)
                    mma_f16(acc[mt][nt], A[mt], &Bm[nt >> 1][(nt & 1) * 2]);
        }
        __syncthreads();
        if (tid == 0 && r + 3 < 9) {
            const int rn = r + 3;
            const int s = (oi + rn / 3) * 32 + (oj + rn % 3);
            const uint32_t mbar = mb + (uint32_t)(rn % 3) * 8;
            MBARRIER_EXPECT_TX(mbar, 24576u);
            bulk_g2s(sb + (uint32_t)(rn % 3) * STAGE,
                     (const char*)g_Xf + (size_t)s * 16384, 16384u, mbar);
            bulk_g2s(sb + (uint32_t)(rn % 3) * STAGE + 16384u,
                     (const char*)g_Wf + (size_t)(pos * 9 + rn) * 8192, 8192u, mbar);
        }
    }

    // ---- epilogue: bias + sector-perfect float2 stores to g_Y[pos][b*64+o] ----
    float bv[4][2];
    #pragma unroll
    for (int nt = 0; nt < 4; nt++)
        #pragma unroll
        for (int cc = 0; cc < 2; cc++)
            bv[nt][cc] = bias[(size_t)(wn * 32 + nt * 8 + (lane & 3) * 2 + cc) * NPOS + pos];
    float* yp = g_Y + (size_t)pos * 8192;
    #pragma unroll
    for (int mt = 0; mt < 2; mt++)
        #pragma unroll
        for (int half = 0; half < 2; half++) {
            const int b = wm * 32 + mt * 16 + (lane >> 2) + half * 8;
            #pragma unroll
            for (int nt = 0; nt < 4; nt++) {
                const int o0 = wn * 32 + nt * 8 + (lane & 3) * 2;
                float2 v;
                v.x = acc[mt][nt][half * 2 + 0] + bv[nt][0];
                v.y = acc[mt][nt][half * 2 + 1] + bv[nt][1];
                *(float2*)(yp + b * 64 + o0) = v;
            }
        }
}

// ============================================================
// Transpose: g_Y[pos][bo] -> out[bo][pos]. 36x128 tiles (exact).
// ============================================================
__global__ __launch_bounds__(256) void lc_tr(float* __restrict__ out) {
    __shared__ float t[36][130];
    const int tid  = threadIdx.x;
    const int pos0 = blockIdx.x * 36;
    const int bo0  = blockIdx.y * 128;
    #pragma unroll
    for (int k = 0; k < 5; k++) {
        int idx = tid + k * 256;
        if (idx < 1152) {
            int p = idx >> 5, q = idx & 31;
            float4 v = *(const float4*)(g_Y + (size_t)(pos0 + p) * 8192 + bo0 + q * 4);
            t[p][q * 4 + 0] = v.x; t[p][q * 4 + 1] = v.y;
            t[p][q * 4 + 2] = v.z; t[p][q * 4 + 3] = v.w;
        }
    }
    __syncthreads();
    #pragma unroll
    for (int k = 0; k < 5; k++) {
        int idx = tid + k * 256;
        if (idx < 1152) {
            int f  = idx % 9;
            int bo = idx / 9;
            float4 v;
            v.x = t[f * 4 + 0][bo];
            v.y = t[f * 4 + 1][bo];
            v.z = t[f * 4 + 2][bo];
            v.w = t[f * 4 + 3][bo];
            *(float4*)(out + (size_t)(bo0 + bo) * NPOS + pos0 + f * 4) = v;
        }
    }
}

// ============================================================
extern "C" void kernel_launch(void* const* d_in, const int* in_sizes, int n_in,
                              void* d_out, int out_size) {
    const float* x    = (const float*)d_in[0];   // [128,64,32,32]
    const float* wt   = (const float*)d_in[1];   // [64,64,30,30,3,3]
    const float* bias = (const float*)d_in[2];   // [64,30,30]
    float* out = (float*)d_out;                  // [128,64,30,30]

    cudaFuncSetAttribute(lc_fused, cudaFuncAttributeMaxDynamicSharedMemorySize, SM_TOTAL);

    lc_reset<<<1, 128>>>();
    lc_fused<<<NXBLK + NWBLK + NPOS, 256, SM_TOTAL>>>(wt, x, bias);
    lc_tr<<<dim3(25, 64), 256>>>(out);
}

// round 16
// speedup vs baseline: 2.7259x; 1.3804x over previous
#include <cuda_runtime.h>
#include <cuda_fp16.h>
#include <cstdint>

// ============================================================
// LocallyConnectedLayer (B=128, C=64, O=64, 30x30 pos, K=3).
// R16 (= R15 resubmit; infra failure last round): R9 verbatim
// (prep -> lc_main(__syncthreads ring) -> lc_tr), with ONLY prep_all
// replaced by the 2-tile software-pipelined version (load tile B into
// regs while storing tile A -> higher DRAM duty cycle).
// ============================================================

#define NPOS 900
#define PW   8100      // NPOS*9

// ---- scratch ----
__device__ __align__(1024) __half g_Wf[(size_t)PW * 64 * 64];   // [P]: 8KB slice [o][c], SW128
__device__ __align__(1024) __half g_Xf[(size_t)1024 * 8192];    // [s]: 16KB slice [b*64+c], SW128
__device__ __align__(1024) float  g_Y[(size_t)NPOS * 8192];     // [pos][b*64+o]

// ---- helpers ----
__device__ __forceinline__ uint32_t smem_to_u32(const void* p) {
    uint32_t a;
    asm("{ .reg .u64 t; cvta.to.shared.u64 t, %1; cvt.u32.u64 %0, t; }" : "=r"(a) : "l"(p));
    return a;
}
#define SWZ(off) ((off) ^ (((off) >> 3) & 0x70))

__device__ __forceinline__ void ldsm_x4(uint32_t a[4], uint32_t addr) {
    asm volatile("ldmatrix.sync.aligned.m8n8.x4.shared.b16 {%0,%1,%2,%3}, [%4];"
        : "=r"(a[0]), "=r"(a[1]), "=r"(a[2]), "=r"(a[3]) : "r"(addr));
}
__device__ __forceinline__ void mma_f16(float c[4], const uint32_t a[4], const uint32_t b[2]) {
    asm volatile(
        "mma.sync.aligned.m16n8k16.row.col.f32.f16.f16.f32 "
        "{%0,%1,%2,%3},{%4,%5,%6,%7},{%8,%9},{%0,%1,%2,%3};"
        : "+f"(c[0]), "+f"(c[1]), "+f"(c[2]), "+f"(c[3])
        : "r"(a[0]), "r"(a[1]), "r"(a[2]), "r"(a[3]), "r"(b[0]), "r"(b[1]));
}
#define MBARRIER_INIT(mbar, count) \
    asm volatile("mbarrier.init.shared.b64 [%0], %1;" :: "r"((uint32_t)(mbar)), "r"((uint32_t)(count)) : "memory")
#define MBARRIER_EXPECT_TX(mbar, tx) \
    asm volatile("mbarrier.arrive.expect_tx.shared.b64 _, [%0], %1;" :: "r"((uint32_t)(mbar)), "r"((uint32_t)(tx)) : "memory")
#define MBARRIER_WAIT_PARITY(mbar, parity) do { \
    uint32_t _m = (uint32_t)(mbar); uint32_t _p = (uint32_t)(parity); uint32_t _d; \
    asm volatile("{\n\t.reg .pred p;\n\tmbarrier.try_wait.parity.acquire.cta.shared::cta.b64 p, [%1], %2;\n\tselp.b32 %0, 1, 0, p;\n\t}" \
        : "=r"(_d) : "r"(_m), "r"(_p) : "memory"); \
    if (!_d) { \
        asm volatile("{\n\t.reg .pred P1;\n\tWL_%=:\n\tmbarrier.try_wait.parity.acquire.cta.shared::cta.b64 P1, [%0], %1, 0x989680;\n\t@P1 bra.uni WD_%=;\n\tbra.uni WL_%=;\n\tWD_%=:\n\t}" \
            :: "r"(_m), "r"(_p) : "memory"); \
    } } while (0)
__device__ __forceinline__ void bulk_g2s(uint32_t dst, const void* src, uint32_t bytes, uint32_t mbar) {
    asm volatile(
        "cp.async.bulk.shared::cluster.global.mbarrier::complete_tx::bytes [%0], [%1], %2, [%3];"
        :: "r"(dst), "l"(src), "r"(bytes), "r"(mbar) : "memory");
}

// ============================================================
// Fused prepass, 2 tiles per block, software pipelined.
// Blocks [0, NWBLK): weight — o = b&63, P-group = b>>6 (128 P-rows).
// Blocks [NWBLK, +1024): x — 64 bc-rows x 128 s-cols (two 64-wide tiles).
// ============================================================
#define NWBLK 4096   // 64 P-groups * 64 o

__device__ __forceinline__ void loadW_regs(float4 r[4], const float* __restrict__ wt,
                                           int o, int P0, int tid) {
    #pragma unroll
    for (int k = 0; k < 4; k++) {
        int idx = tid + k * 256;
        int c   = idx >> 4;
        int q   = idx & 15;
        int P   = P0 + q * 4;
        const float* src = wt + (size_t)(c * 64 + o) * PW + P;
        if (P + 3 < PW) r[k] = *(const float4*)src;
        else {
            r[k].x = (P     < PW) ? src[0] : 0.f;
            r[k].y = (P + 1 < PW) ? src[1] : 0.f;
            r[k].z = (P + 2 < PW) ? src[2] : 0.f;
            r[k].w = (P + 3 < PW) ? src[3] : 0.f;
        }
    }
}
__device__ __forceinline__ void stage_regs(float (*t)[65], const float4 r[4], int tid) {
    #pragma unroll
    for (int k = 0; k < 4; k++) {
        int idx = tid + k * 256;
        int row = idx >> 4;
        int q   = idx & 15;
        t[row][q * 4 + 0] = r[k].x; t[row][q * 4 + 1] = r[k].y;
        t[row][q * 4 + 2] = r[k].z; t[row][q * 4 + 3] = r[k].w;
    }
}
__device__ __forceinline__ void storeW_tile(const float (*t)[65], int o, int P0, int tid) {
    #pragma unroll
    for (int k = 0; k < 2; k++) {
        int idx = tid + k * 256;
        int pl  = idx >> 3;
        int q8  = idx & 7;
        int P   = P0 + pl;
        if (P < PW) {
            uint32_t pk[4];
            #pragma unroll
            for (int j = 0; j < 4; j++) {
                __half2 h = __floats2half2_rn(t[q8 * 8 + j * 2][pl], t[q8 * 8 + j * 2 + 1][pl]);
                pk[j] = *(uint32_t*)&h;
            }
            uint32_t off = SWZ((uint32_t)(o * 128 + q8 * 16));
            *(uint4*)((char*)g_Wf + (size_t)P * 8192 + off) = *(uint4*)pk;
        }
    }
}
__device__ __forceinline__ void loadX_regs(float4 r[4], const float* __restrict__ x,
                                           int bc0, int s0, int tid) {
    #pragma unroll
    for (int k = 0; k < 4; k++) {
        int idx = tid + k * 256;
        int rr  = idx >> 4;
        int q   = idx & 15;
        r[k] = *(const float4*)(x + (size_t)(bc0 + rr) * 1024 + s0 + q * 4);
    }
}
__device__ __forceinline__ void storeX_tile(const float (*t)[65], int bc0, int s0, int tid) {
    #pragma unroll
    for (int k = 0; k < 2; k++) {
        int idx = tid + k * 256;
        int sl  = idx >> 3;
        int q8  = idx & 7;
        uint32_t pk[4];
        #pragma unroll
        for (int j = 0; j < 4; j++) {
            __half2 h = __floats2half2_rn(t[q8 * 8 + j * 2][sl], t[q8 * 8 + j * 2 + 1][sl]);
            pk[j] = *(uint32_t*)&h;
        }
        uint32_t off = SWZ((uint32_t)(bc0 * 2 + q8 * 16));
        *(uint4*)((char*)g_Xf + (size_t)(s0 + sl) * 16384 + off) = *(uint4*)pk;
    }
}

__global__ __launch_bounds__(256) void prep_all(const float* __restrict__ wt,
                                                const float* __restrict__ x) {
    __shared__ float t[2][64][65];
    const int tid = threadIdx.x;
    float4 r0[4], r1[4];
    if (blockIdx.x < NWBLK) {
        const int o  = blockIdx.x & 63;
        const int P0 = (blockIdx.x >> 6) * 128;
        loadW_regs(r0, wt, o, P0, tid);
        stage_regs(t[0], r0, tid);
        __syncthreads();
        loadW_regs(r1, wt, o, P0 + 64, tid);   // LDGs in flight during store A
        storeW_tile(t[0], o, P0, tid);
        stage_regs(t[1], r1, tid);
        __syncthreads();
        storeW_tile(t[1], o, P0 + 64, tid);
    } else {
        const int i   = blockIdx.x - NWBLK;    // 0..1023
        const int s0  = (i & 7) * 128;
        const int bc0 = (i >> 3) * 64;
        loadX_regs(r0, x, bc0, s0, tid);
        stage_regs(t[0], r0, tid);
        __syncthreads();
        loadX_regs(r1, x, bc0, s0 + 64, tid);
        storeX_tile(t[0], bc0, s0, tid);
        stage_regs(t[1], r1, tid);
        __syncthreads();
        storeX_tile(t[1], bc0, s0 + 64, tid);
    }
}

// ============================================================
// Main (R9 verbatim): 900 CTAs, 256 threads (4x2 warps, 32x32 warp tile).
// 9 steps; 3-stage 24KB ring = 72KB -> 3 CTAs/SM; __syncthreads ring.
// ============================================================
#define STAGE 24576u
#define SM_TOTAL (3 * 24576)

__device__ __forceinline__ void issue_step(uint32_t sb, uint32_t mb, int pos,
                                           int oi, int oj, int r) {
    const int s = (oi + r / 3) * 32 + (oj + r % 3);
    const int b = r % 3;
    const uint32_t dst  = sb + (uint32_t)b * STAGE;
    const uint32_t mbar = mb + (uint32_t)b * 8;
    MBARRIER_EXPECT_TX(mbar, 24576u);
    bulk_g2s(dst,          (const char*)g_Xf + (size_t)s * 16384, 16384u, mbar);
    bulk_g2s(dst + 16384u, (const char*)g_Wf + (size_t)(pos * 9 + r) * 8192, 8192u, mbar);
}

__global__ __launch_bounds__(256, 3) void lc_main(const float* __restrict__ bias) {
    extern __shared__ __align__(1024) char smem[];
    __shared__ __align__(8) uint64_t mbar_s[3];
    const uint32_t sb = smem_to_u32(smem);
    const uint32_t mb = smem_to_u32(mbar_s);
    const int tid  = threadIdx.x;
    const int lane = tid & 31;
    const int warp = tid >> 5;
    const int wm   = warp & 3;    // 4 warps along M (batch)
    const int wn   = warp >> 2;   // 2 warps along N (out-ch)
    const int pos  = blockIdx.x;
    const int oi   = pos / 30;
    const int oj   = pos % 30;

    if (tid == 0) {
        MBARRIER_INIT(mb, 1); MBARRIER_INIT(mb + 8, 1); MBARRIER_INIT(mb + 16, 1);
    }
    __syncthreads();

    if (tid == 0) {
        issue_step(sb, mb, pos, oi, oj, 0);
        issue_step(sb, mb, pos, oi, oj, 1);
        issue_step(sb, mb, pos, oi, oj, 2);
    }

    const int rowA = lane & 15;
    const uint32_t a_cs = (uint32_t)(lane >> 4) * 16;
    const uint32_t a_xm = (uint32_t)(rowA & 7) << 4;
    uint32_t a_row[2];
    #pragma unroll
    for (int mt = 0; mt < 2; mt++)
        a_row[mt] = (uint32_t)(wm * 32 + mt * 16 + rowA) * 128;

    const int rowB = (lane & 7) + ((lane >> 4) << 3);
    const uint32_t b_cs = (uint32_t)((lane >> 3) & 1) * 16;
    const uint32_t b_xm = (uint32_t)(lane & 7) << 4;
    uint32_t b_row[2];
    #pragma unroll
    for (int np = 0; np < 2; np++)
        b_row[np] = (uint32_t)(wn * 32 + np * 16 + rowB) * 128;

    float acc[2][4][4];
    #pragma unroll
    for (int mt = 0; mt < 2; mt++)
        #pragma unroll
        for (int nt = 0; nt < 4; nt++)
            #pragma unroll
            for (int e = 0; e < 4; e++) acc[mt][nt][e] = 0.f;

    uint32_t ph = 0;
    for (int r = 0; r < 9; r++) {
        const int b = r % 3;
        const uint32_t pb = (ph >> b) & 1u;
        ph ^= 1u << b;
        MBARRIER_WAIT_PARITY(mb + (uint32_t)b * 8, pb);
        const uint32_t abase = sb + (uint32_t)b * STAGE;
        const uint32_t wbase = abase + 16384u;
        #pragma unroll
        for (int kk = 0; kk < 4; kk++) {
            const uint32_t acol = ((uint32_t)(kk * 32) + a_cs) ^ a_xm;
            const uint32_t bcol = ((uint32_t)(kk * 32) + b_cs) ^ b_xm;
            uint32_t A[2][4], Bm[2][4];
            #pragma unroll
            for (int mt = 0; mt < 2; mt++)
                ldsm_x4(A[mt], abase + a_row[mt] + acol);
            #pragma unroll
            for (int np = 0; np < 2; np++)
                ldsm_x4(Bm[np], wbase + b_row[np] + bcol);
            #pragma unroll
            for (int mt = 0; mt < 2; mt++)
                #pragma unroll
                for (int nt = 0; nt < 4; nt++)
                    mma_f16(acc[mt][nt], A[mt], &Bm[nt >> 1][(nt & 1) * 2]);
        }
        __syncthreads();
        if (tid == 0 && r + 3 < 9) issue_step(sb, mb, pos, oi, oj, r + 3);
    }

    // ---- epilogue: bias + sector-perfect float2 stores to g_Y[pos][b*64+o] ----
    float bv[4][2];
    #pragma unroll
    for (int nt = 0; nt < 4; nt++)
        #pragma unroll
        for (int cc = 0; cc < 2; cc++)
            bv[nt][cc] = bias[(size_t)(wn * 32 + nt * 8 + (lane & 3) * 2 + cc) * NPOS + pos];
    float* yp = g_Y + (size_t)pos * 8192;
    #pragma unroll
    for (int mt = 0; mt < 2; mt++)
        #pragma unroll
        for (int half = 0; half < 2; half++) {
            const int b = wm * 32 + mt * 16 + (lane >> 2) + half * 8;
            #pragma unroll
            for (int nt = 0; nt < 4; nt++) {
                const int o0 = wn * 32 + nt * 8 + (lane & 3) * 2;
                float2 v;
                v.x = acc[mt][nt][half * 2 + 0] + bv[nt][0];
                v.y = acc[mt][nt][half * 2 + 1] + bv[nt][1];
                *(float2*)(yp + b * 64 + o0) = v;
            }
        }
}

// ============================================================
// Transpose: g_Y[pos][bo] -> out[bo][pos]. 36x128 tiles (exact).
// ============================================================
__global__ __launch_bounds__(256) void lc_tr(float* __restrict__ out) {
    __shared__ float t[36][130];
    const int tid  = threadIdx.x;
    const int pos0 = blockIdx.x * 36;
    const int bo0  = blockIdx.y * 128;
    #pragma unroll
    for (int k = 0; k < 5; k++) {
        int idx = tid + k * 256;
        if (idx < 1152) {
            int p = idx >> 5, q = idx & 31;
            float4 v = *(const float4*)(g_Y + (size_t)(pos0 + p) * 8192 + bo0 + q * 4);
            t[p][q * 4 + 0] = v.x; t[p][q * 4 + 1] = v.y;
            t[p][q * 4 + 2] = v.z; t[p][q * 4 + 3] = v.w;
        }
    }
    __syncthreads();
    #pragma unroll
    for (int k = 0; k < 5; k++) {
        int idx = tid + k * 256;
        if (idx < 1152) {
            int f  = idx % 9;
            int bo = idx / 9;
            float4 v;
            v.x = t[f * 4 + 0][bo];
            v.y = t[f * 4 + 1][bo];
            v.z = t[f * 4 + 2][bo];
            v.w = t[f * 4 + 3][bo];
            *(float4*)(out + (size_t)(bo0 + bo) * NPOS + pos0 + f * 4) = v;
        }
    }
}

// ============================================================
extern "C" void kernel_launch(void* const* d_in, const int* in_sizes, int n_in,
                              void* d_out, int out_size) {
    const float* x    = (const float*)d_in[0];   // [128,64,32,32]
    const float* wt   = (const float*)d_in[1];   // [64,64,30,30,3,3]
    const float* bias = (const float*)d_in[2];   // [64,30,30]
    float* out = (float*)d_out;                  // [128,64,30,30]

    cudaFuncSetAttribute(lc_main, cudaFuncAttributeMaxDynamicSharedMemorySize, SM_TOTAL);

    prep_all<<<NWBLK + 1024, 256>>>(wt, x);
    lc_main<<<NPOS, 256, SM_TOTAL>>>(bias);
    lc_tr<<<dim3(25, 64), 256>>>(out);
}